// round 14
// baseline (speedup 1.0000x reference)
#include <cuda_runtime.h>
#include <cuda_bf16.h>
#include <cstdint>

// Problem constants
#define B_      2
#define L_      64
#define D_      1024
#define H_      512
#define S_      50000
#define V_      40000
#define K_      32
#define M_      128          // B_*L_
#define SLM_SCALE 0.1f
#define BN_EPS  1e-5f

typedef unsigned long long ull;

// ---------------- PTX helpers (target-suffix-free; valid on compute_103) ----------
static __device__ __forceinline__ void ldsm_x4(uint32_t* r, uint32_t addr) {
    asm volatile("ldmatrix.sync.aligned.m8n8.x4.shared.b16 {%0,%1,%2,%3}, [%4];"
                 : "=r"(r[0]), "=r"(r[1]), "=r"(r[2]), "=r"(r[3]) : "r"(addr));
}
static __device__ __forceinline__ void ldsm_x4_t(uint32_t* r, uint32_t addr) {
    asm volatile("ldmatrix.sync.aligned.m8n8.x4.trans.shared.b16 {%0,%1,%2,%3}, [%4];"
                 : "=r"(r[0]), "=r"(r[1]), "=r"(r[2]), "=r"(r[3]) : "r"(addr));
}
static __device__ __forceinline__ void mma16816(float* c, const uint32_t* a,
                                                uint32_t b0, uint32_t b1) {
    asm volatile("mma.sync.aligned.m16n8k16.row.col.f32.bf16.bf16.f32 "
                 "{%0,%1,%2,%3}, {%4,%5,%6,%7}, {%8,%9}, {%0,%1,%2,%3};"
                 : "+f"(c[0]), "+f"(c[1]), "+f"(c[2]), "+f"(c[3])
                 : "r"(a[0]), "r"(a[1]), "r"(a[2]), "r"(a[3]), "r"(b0), "r"(b1));
}
static __device__ __forceinline__ void cpa16(uint32_t dst, const void* src) {
    asm volatile("cp.async.cg.shared.global [%0], [%1], 16;" :: "r"(dst), "l"(src) : "memory");
}
static __device__ __forceinline__ void cpa_commit() {
    asm volatile("cp.async.commit_group;" ::: "memory");
}
static __device__ __forceinline__ void cpa_wait0() {
    asm volatile("cp.async.wait_group 0;" ::: "memory");
}
static __device__ __forceinline__ void sts64(uint32_t addr, uint32_t lo, uint32_t hi) {
    asm volatile("st.shared.v2.b32 [%0], {%1, %2};" :: "r"(addr), "r"(lo), "r"(hi) : "memory");
}

// ---------------- scratch (device globals; no allocation allowed) ----------------
__device__ float g_scale[L_];
__device__ float g_shift[L_];
// h as bf16 hi/lo, [128 m][512 k] row-major (k contiguous) — cp.async-ready
__device__ __align__(16) __nv_bfloat16 g_hhi[M_ * H_];
__device__ __align__(16) __nv_bfloat16 g_hlo[M_ * H_];
// v^T as bf16: [40000 n][128 m]
__device__ __align__(16) __nv_bfloat16 g_vt16[V_ * M_];

// ---------------- Kernel 1: BatchNorm stats ----------------
__global__ __launch_bounds__(256)
void bn_stats_kernel(const float* __restrict__ x,
                     const float* __restrict__ gamma,
                     const float* __restrict__ beta)
{
    const int l = blockIdx.x;
    const float* p0 = x + (size_t)l * D_;
    const float* p1 = x + (size_t)(L_ + l) * D_;
    float s = 0.f, sq = 0.f;
    for (int i = threadIdx.x; i < D_; i += 256) {
        float a = p0[i], b = p1[i];
        s  += a + b;
        sq += a * a + b * b;
    }
    __shared__ float rs[256], rq[256];
    rs[threadIdx.x] = s; rq[threadIdx.x] = sq;
    __syncthreads();
    for (int off = 128; off > 0; off >>= 1) {
        if (threadIdx.x < off) {
            rs[threadIdx.x] += rs[threadIdx.x + off];
            rq[threadIdx.x] += rq[threadIdx.x + off];
        }
        __syncthreads();
    }
    if (threadIdx.x == 0) {
        const float inv_n = 1.f / (float)(B_ * D_);
        float mean = rs[0] * inv_n;
        float var  = rq[0] * inv_n - mean * mean;
        float rstd = rsqrtf(var + BN_EPS);
        float sc = gamma[l] * rstd;
        g_scale[l] = sc;
        g_shift[l] = beta[l] - mean * sc;
    }
}

// ---------------- Kernel 2: h = relu(xn @ W1 + b1) -> bf16 hi/lo [m][k] ----------------
__global__ __launch_bounds__(256)
void h_gemm_kernel(const float* __restrict__ x,
                   const float* __restrict__ W1,
                   const float* __restrict__ b1)
{
    __shared__ float sSc[64], sSh[64];
    __shared__ float Ast[64 * 33];
    __shared__ float Bst[32 * 32];
    const int tid = threadIdx.x;
    const int m0 = blockIdx.x * 64;
    const int n0 = blockIdx.y * 32;
    if (tid < 64) { sSc[tid] = g_scale[tid]; sSh[tid] = g_shift[tid]; }
    __syncthreads();
    const int mg = tid >> 4;
    const int ng = tid & 15;
    float acc[4][2] = {};
    for (int k0 = 0; k0 < D_; k0 += 32) {
        #pragma unroll
        for (int i = 0; i < 8; ++i) {
            int e = tid + i * 256;
            int mi = e >> 5, ki = e & 31;
            float v = x[(size_t)(m0 + mi) * D_ + k0 + ki];
            Ast[mi * 33 + ki] = v * sSc[mi] + sSh[mi];
        }
        #pragma unroll
        for (int i = 0; i < 4; ++i) {
            int e = tid + i * 256;
            int ki = e >> 5, ni = e & 31;
            Bst[ki * 32 + ni] = W1[(size_t)(k0 + ki) * H_ + n0 + ni];
        }
        __syncthreads();
        #pragma unroll
        for (int kk = 0; kk < 32; ++kk) {
            float b0 = Bst[kk * 32 + ng * 2];
            float b1v = Bst[kk * 32 + ng * 2 + 1];
            #pragma unroll
            for (int i = 0; i < 4; ++i) {
                float a = Ast[(mg * 4 + i) * 33 + kk];
                acc[i][0] = fmaf(a, b0, acc[i][0]);
                acc[i][1] = fmaf(a, b1v, acc[i][1]);
            }
        }
        __syncthreads();
    }
    #pragma unroll
    for (int j = 0; j < 2; ++j) {
        int n = n0 + ng * 2 + j;          // hidden index = k of big GEMMs
        float bb = b1[n];
        #pragma unroll
        for (int i = 0; i < 4; ++i) {
            int m = m0 + mg * 4 + i;
            float hv = fmaxf(acc[i][j] + bb, 0.f);
            __nv_bfloat16 hi = __float2bfloat16(hv);
            __nv_bfloat16 lo = __float2bfloat16(hv - __bfloat162float(hi));
            g_hhi[(size_t)m * H_ + n] = hi;
            g_hlo[(size_t)m * H_ + n] = lo;
        }
    }
}

// ---------------- Kernels 3 & 4: wide-tile bf16 hi/lo HMMA GEMM ------------------------
// 512 threads (16 warps: 4m x 4n), CTA tile M=128 x N=128, KC=32, 16 chunks.
// Per-warp tile m32 x n32 -> 48 MMA vs 16 ldsm per chunk = 12 MAC/smem-byte
// (vs 9.6 before): smem crossbar no longer the binder.
// Per-stage smem (37,888 B; 2 stages = 75,776 B):
//   +0      Ah [128 m][40] bf16 (80 B rows)    10,240 B
//   +10240  Al                                 10,240 B
//   +20480  Bh [32 k][136] bf16 (272 B rows)    8,704 B
//   +29184  Bl                                  8,704 B
// W path register-resident (2 float4/thread); 1 bar per chunk (R12 scheme).
#define KC_    32
#define NCH    (H_ / KC_)          // 16
#define AROWB  80
#define BROWB  272
#define OFF_AL 10240
#define OFF_BH 20480
#define OFF_BL 29184
#define STG    37888

template<int MODE>
__global__ __launch_bounds__(512, 1)
void mma_gemm_kernel(const float* __restrict__ W,
                     const float* __restrict__ bias,
                     const float* __restrict__ slw,
                     const int*   __restrict__ slidx,
                     float* __restrict__ out,
                     int Nfull)
{
    extern __shared__ __align__(16) unsigned char dynsmem[];
    __shared__ int   sIdx[16][32];
    __shared__ float sWt[16][32];

    const int tid = threadIdx.x;
    const int wid = tid >> 5;
    const int lid = tid & 31;
    const int wm = wid >> 2;            // 0..3 -> m offset wm*32
    const int wn = wid & 3;             // 0..3 -> n offset wn*32
    const int n0 = blockIdx.x * 128;

    const uint32_t sb = (uint32_t)__cvta_generic_to_shared(dynsmem);

    // this thread's two W granules: e = tid, tid+512; k = e>>5, n4 = (e&31)*4
    const int k_a = tid >> 5,          n4_g = (tid & 31) * 4;
    const int k_b = (tid + 512) >> 5;
    const bool okN = (n0 + n4_g < Nfull);    // Nfull % 4 == 0 -> granule all-or-nothing

    float4 wra, wrb;                         // W prefetch registers

    auto ldg_w = [&](int c) {
        const float* Wc = W + (size_t)(c * KC_) * Nfull + n0 + n4_g;
        wra = okN ? *(const float4*)(Wc + (size_t)k_a * Nfull) : make_float4(0.f,0.f,0.f,0.f);
        wrb = okN ? *(const float4*)(Wc + (size_t)k_b * Nfull) : make_float4(0.f,0.f,0.f,0.f);
    };
    auto sts_b = [&](int buf) {
        const uint32_t base = sb + buf * STG;
        #pragma unroll
        for (int t = 0; t < 2; ++t) {
            float4 wv = t ? wrb : wra;
            int k = t ? k_b : k_a;
            __nv_bfloat162 h01 = __floats2bfloat162_rn(wv.x, wv.y);
            __nv_bfloat162 h23 = __floats2bfloat162_rn(wv.z, wv.w);
            float2 fh01 = __bfloat1622float2(h01);
            float2 fh23 = __bfloat1622float2(h23);
            __nv_bfloat162 l01 = __floats2bfloat162_rn(wv.x - fh01.x, wv.y - fh01.y);
            __nv_bfloat162 l23 = __floats2bfloat162_rn(wv.z - fh23.x, wv.w - fh23.y);
            uint32_t d = k * BROWB + n4_g * 2;
            sts64(base + OFF_BH + d, *reinterpret_cast<uint32_t*>(&h01),
                                     *reinterpret_cast<uint32_t*>(&h23));
            sts64(base + OFF_BL + d, *reinterpret_cast<uint32_t*>(&l01),
                                     *reinterpret_cast<uint32_t*>(&l23));
        }
    };
    auto issue_a = [&](int c, int buf) {
        const uint32_t base = sb + buf * STG;
        const int k0b = c * KC_ * 2;
        int m = tid >> 2, g = tid & 3;       // one granule per thread per tile
        uint32_t d = m * AROWB + g * 16;
        cpa16(base + d,          (const char*)g_hhi + (size_t)m * (H_ * 2) + k0b + g * 16);
        cpa16(base + OFF_AL + d, (const char*)g_hlo + (size_t)m * (H_ * 2) + k0b + g * 16);
        cpa_commit();
    };

    float acc[2][4][4];
    #pragma unroll
    for (int t = 0; t < 2; ++t)
        #pragma unroll
        for (int u = 0; u < 4; ++u)
            #pragma unroll
            for (int q = 0; q < 4; ++q) acc[t][u][q] = 0.f;

    // ---- prologue ----
    ldg_w(0);
    sts_b(0);
    issue_a(0, 0);
    ldg_w(1);
    cpa_wait0();
    __syncthreads();          // A(0), B(0) visible
    issue_a(1, 1);

    for (int c = 0; c < NCH; ++c) {
        const int buf = c & 1;
        const uint32_t base = sb + buf * STG;

        if (c + 1 < NCH) sts_b((c + 1) & 1);   // publish B(c+1) (own regs)
        if (c + 2 < NCH) ldg_w(c + 2);         // W prefetch hides under MMA below

        // ---- MMA(c): 2 k16 steps x 2 m-tiles x 12 MMAs ----
        #pragma unroll
        for (int ks = 0; ks < 2; ++ks) {
            uint32_t brow = base + OFF_BH
                + (uint32_t)((ks * 16 + (lid & 7) + ((lid >> 3) & 1) * 8) * BROWB
                             + (wn * 32 + (lid >> 4) * 8) * 2);
            uint32_t bh[8], bl[8];
            ldsm_x4_t(bh,     brow);
            ldsm_x4_t(bh + 4, brow + 32);                  // +16 n cols
            ldsm_x4_t(bl,     brow + (OFF_BL - OFF_BH));
            ldsm_x4_t(bl + 4, brow + (OFF_BL - OFF_BH) + 32);
            #pragma unroll
            for (int t = 0; t < 2; ++t) {
                uint32_t aaddr = base
                    + (uint32_t)((wm * 32 + t * 16 + (lid & 15)) * AROWB
                                 + (ks * 16 + (lid >> 4) * 8) * 2);
                uint32_t ah[4], al[4];
                ldsm_x4(ah, aaddr);
                ldsm_x4(al, aaddr + OFF_AL);
                #pragma unroll
                for (int u = 0; u < 4; ++u) {
                    mma16816(acc[t][u], ah, bh[2*u], bh[2*u+1]);
                    mma16816(acc[t][u], ah, bl[2*u], bl[2*u+1]);
                    mma16816(acc[t][u], al, bh[2*u], bh[2*u+1]);
                }
            }
        }

        if (c + 1 < NCH) cpa_wait0();          // A(c+1) resident
        __syncthreads();                       // rotate; publish B(c+1)/A(c+1)
        if (c + 2 < NCH) issue_a(c + 2, buf);  // A(c) readers done
    }

    // ---------------- epilogues (reuse dynsmem) ----------------
    if (MODE == 0) {
        float* Ct = (float*)dynsmem;               // [128 n][132 m]
        #pragma unroll
        for (int t = 0; t < 2; ++t)
            #pragma unroll
            for (int u = 0; u < 4; ++u) {
                int row = wm * 32 + t * 16 + (lid >> 2);
                int col = wn * 32 + u * 8 + (lid & 3) * 2;
                Ct[(col    ) * 132 + row    ] = acc[t][u][0];
                Ct[(col + 1) * 132 + row    ] = acc[t][u][1];
                Ct[(col    ) * 132 + row + 8] = acc[t][u][2];
                Ct[(col + 1) * 132 + row + 8] = acc[t][u][3];
            }
        __syncthreads();
        #pragma unroll
        for (int it = 0; it < 8; ++it) {
            int e = tid + it * 512;                // 128 n x 32 m-quads
            int nl = e >> 5, mu = (e & 31) * 4;
            int n = n0 + nl;
            if (n < Nfull) {
                float bs = bias[n];
                float4 v = *(const float4*)&Ct[nl * 132 + mu];
                __nv_bfloat162 p0 = __floats2bfloat162_rn(v.x + bs, v.y + bs);
                __nv_bfloat162 p1 = __floats2bfloat162_rn(v.z + bs, v.w + bs);
                uint2 pk;
                pk.x = *reinterpret_cast<uint32_t*>(&p0);
                pk.y = *reinterpret_cast<uint32_t*>(&p1);
                *(uint2*)(g_vt16 + (size_t)n * M_ + mu) = pk;
            }
        }
    } else {
        float* Cs = (float*)dynsmem;               // [128 m][132 n]
        #pragma unroll
        for (int t = 0; t < 2; ++t)
            #pragma unroll
            for (int u = 0; u < 4; ++u) {
                int row = wm * 32 + t * 16 + (lid >> 2);
                int col = wn * 32 + u * 8 + (lid & 3) * 2;
                Cs[(row    ) * 132 + col    ] = acc[t][u][0];
                Cs[(row    ) * 132 + col + 1] = acc[t][u][1];
                Cs[(row + 8) * 132 + col    ] = acc[t][u][2];
                Cs[(row + 8) * 132 + col + 1] = acc[t][u][3];
            }
        __syncthreads();

        // coalesced sparse gather-add (512B/warp g_vt16 reads)
        #pragma unroll 1
        for (int si = 0; si < 8; ++si) {
            int nl = wid * 8 + si;
            int s = n0 + nl;
            if (s < Nfull) {                       // warp-uniform
                sIdx[wid][lid] = slidx[(size_t)s * K_ + lid];
                sWt[wid][lid]  = slw  [(size_t)s * K_ + lid] * SLM_SCALE;
                __syncwarp();
                float ax = 0.f, ay = 0.f, az = 0.f, aw = 0.f;
                #pragma unroll
                for (int k = 0; k < K_; ++k) {
                    int   ix = sIdx[wid][k];
                    float wk = sWt[wid][k];
                    uint2 pk = *(const uint2*)(g_vt16 + (size_t)ix * M_ + lid * 4);
                    __nv_bfloat162 q0 = *reinterpret_cast<__nv_bfloat162*>(&pk.x);
                    __nv_bfloat162 q1 = *reinterpret_cast<__nv_bfloat162*>(&pk.y);
                    float2 f0 = __bfloat1622float2(q0);
                    float2 f1 = __bfloat1622float2(q1);
                    ax = fmaf(wk, f0.x, ax);
                    ay = fmaf(wk, f0.y, ay);
                    az = fmaf(wk, f1.x, az);
                    aw = fmaf(wk, f1.y, aw);
                }
                int mB = lid * 4;
                Cs[(mB + 0) * 132 + nl] += ax;
                Cs[(mB + 1) * 132 + nl] += ay;
                Cs[(mB + 2) * 132 + nl] += az;
                Cs[(mB + 3) * 132 + nl] += aw;
                __syncwarp();
            }
        }
        __syncthreads();
        // final store: float4 along n (Nfull % 4 == 0 -> all-or-nothing granules)
        #pragma unroll
        for (int it = 0; it < 8; ++it) {
            int e = tid + it * 512;                // 128 m x 32 n-quads
            int m = e >> 5, n4 = (e & 31) * 4;
            int n = n0 + n4;
            if (n < Nfull) {
                float4 cv = *(const float4*)&Cs[m * 132 + n4];
                float4 bv = *(const float4*)(bias + n);
                float4 o = make_float4(cv.x + bv.x, cv.y + bv.y, cv.z + bv.z, cv.w + bv.w);
                *(float4*)(out + (size_t)m * Nfull + n) = o;
            }
        }
    }
}

// ---------------- launch ----------------
extern "C" void kernel_launch(void* const* d_in, const int* in_sizes, int n_in,
                              void* d_out, int out_size)
{
    const float* x     = (const float*)d_in[0];   // cached_embeddings [2,64,1024]
    const float* gamma = (const float*)d_in[1];   // bn_gamma [64]
    const float* beta  = (const float*)d_in[2];   // bn_beta  [64]
    const float* W1    = (const float*)d_in[3];   // [1024,512]
    const float* b1    = (const float*)d_in[4];   // [512]
    const float* W2    = (const float*)d_in[5];   // [512,50000]
    const float* b2    = (const float*)d_in[6];   // [50000]
    const float* Wslm  = (const float*)d_in[7];   // [512,40000]
    const float* bslm  = (const float*)d_in[8];   // [40000]
    const float* slw   = (const float*)d_in[9];   // [50000,32]
    const int*   slidx = (const int*)d_in[10];    // [50000,32]
    float* out = (float*)d_out;

    const int DYN = 2 * STG;                      // 75,776 B
    cudaFuncSetAttribute(mma_gemm_kernel<0>, cudaFuncAttributeMaxDynamicSharedMemorySize, DYN);
    cudaFuncSetAttribute(mma_gemm_kernel<1>, cudaFuncAttributeMaxDynamicSharedMemorySize, DYN);

    bn_stats_kernel<<<L_, 256>>>(x, gamma, beta);
    h_gemm_kernel<<<dim3(2, 16), 256>>>(x, W1, b1);
    mma_gemm_kernel<0><<<(V_ + 127) / 128, 512, DYN>>>(Wslm, bslm, nullptr, nullptr, nullptr, V_);
    mma_gemm_kernel<1><<<(S_ + 127) / 128, 512, DYN>>>(W2, b2, slw, slidx, out, S_);
}

// round 15
// speedup vs baseline: 1.1617x; 1.1617x over previous
#include <cuda_runtime.h>
#include <cuda_bf16.h>
#include <cstdint>

// Problem constants
#define B_      2
#define L_      64
#define D_      1024
#define H_      512
#define S_      50000
#define V_      40000
#define K_      32
#define M_      128          // B_*L_
#define SLM_SCALE 0.1f
#define BN_EPS  1e-5f

typedef unsigned long long ull;

// ---------------- PTX helpers (target-suffix-free; valid on compute_103) ----------
static __device__ __forceinline__ void ldsm_x4(uint32_t* r, uint32_t addr) {
    asm volatile("ldmatrix.sync.aligned.m8n8.x4.shared.b16 {%0,%1,%2,%3}, [%4];"
                 : "=r"(r[0]), "=r"(r[1]), "=r"(r[2]), "=r"(r[3]) : "r"(addr));
}
static __device__ __forceinline__ void ldsm_x4_t(uint32_t* r, uint32_t addr) {
    asm volatile("ldmatrix.sync.aligned.m8n8.x4.trans.shared.b16 {%0,%1,%2,%3}, [%4];"
                 : "=r"(r[0]), "=r"(r[1]), "=r"(r[2]), "=r"(r[3]) : "r"(addr));
}
static __device__ __forceinline__ void mma16816(float* c, const uint32_t* a,
                                                uint32_t b0, uint32_t b1) {
    asm volatile("mma.sync.aligned.m16n8k16.row.col.f32.bf16.bf16.f32 "
                 "{%0,%1,%2,%3}, {%4,%5,%6,%7}, {%8,%9}, {%0,%1,%2,%3};"
                 : "+f"(c[0]), "+f"(c[1]), "+f"(c[2]), "+f"(c[3])
                 : "r"(a[0]), "r"(a[1]), "r"(a[2]), "r"(a[3]), "r"(b0), "r"(b1));
}
static __device__ __forceinline__ void cpa16(uint32_t dst, const void* src) {
    asm volatile("cp.async.cg.shared.global [%0], [%1], 16;" :: "r"(dst), "l"(src) : "memory");
}
static __device__ __forceinline__ void cpa_commit() {
    asm volatile("cp.async.commit_group;" ::: "memory");
}
static __device__ __forceinline__ void cpa_wait0() {
    asm volatile("cp.async.wait_group 0;" ::: "memory");
}
static __device__ __forceinline__ void sts64(uint32_t addr, uint32_t lo, uint32_t hi) {
    asm volatile("st.shared.v2.b32 [%0], {%1, %2};" :: "r"(addr), "r"(lo), "r"(hi) : "memory");
}

// ---------------- scratch (device globals; no allocation allowed) ----------------
__device__ float g_scale[L_];
__device__ float g_shift[L_];
// h as bf16 hi/lo, [128 m][512 k] row-major (k contiguous) — cp.async-ready
__device__ __align__(16) __nv_bfloat16 g_hhi[M_ * H_];
__device__ __align__(16) __nv_bfloat16 g_hlo[M_ * H_];
// v^T as bf16: [40000 n][128 m]
__device__ __align__(16) __nv_bfloat16 g_vt16[V_ * M_];

// ---------------- Kernel 1: BatchNorm stats ----------------
__global__ __launch_bounds__(256)
void bn_stats_kernel(const float* __restrict__ x,
                     const float* __restrict__ gamma,
                     const float* __restrict__ beta)
{
    const int l = blockIdx.x;
    const float* p0 = x + (size_t)l * D_;
    const float* p1 = x + (size_t)(L_ + l) * D_;
    float s = 0.f, sq = 0.f;
    for (int i = threadIdx.x; i < D_; i += 256) {
        float a = p0[i], b = p1[i];
        s  += a + b;
        sq += a * a + b * b;
    }
    __shared__ float rs[256], rq[256];
    rs[threadIdx.x] = s; rq[threadIdx.x] = sq;
    __syncthreads();
    for (int off = 128; off > 0; off >>= 1) {
        if (threadIdx.x < off) {
            rs[threadIdx.x] += rs[threadIdx.x + off];
            rq[threadIdx.x] += rq[threadIdx.x + off];
        }
        __syncthreads();
    }
    if (threadIdx.x == 0) {
        const float inv_n = 1.f / (float)(B_ * D_);
        float mean = rs[0] * inv_n;
        float var  = rq[0] * inv_n - mean * mean;
        float rstd = rsqrtf(var + BN_EPS);
        float sc = gamma[l] * rstd;
        g_scale[l] = sc;
        g_shift[l] = beta[l] - mean * sc;
    }
}

// ---------------- Kernel 2: h = relu(xn @ W1 + b1) -> bf16 hi/lo [m][k] ----------------
__global__ __launch_bounds__(256)
void h_gemm_kernel(const float* __restrict__ x,
                   const float* __restrict__ W1,
                   const float* __restrict__ b1)
{
    __shared__ float sSc[64], sSh[64];
    __shared__ float Ast[64 * 33];
    __shared__ float Bst[32 * 32];
    const int tid = threadIdx.x;
    const int m0 = blockIdx.x * 64;
    const int n0 = blockIdx.y * 32;
    if (tid < 64) { sSc[tid] = g_scale[tid]; sSh[tid] = g_shift[tid]; }
    __syncthreads();
    const int mg = tid >> 4;
    const int ng = tid & 15;
    float acc[4][2] = {};
    for (int k0 = 0; k0 < D_; k0 += 32) {
        #pragma unroll
        for (int i = 0; i < 8; ++i) {
            int e = tid + i * 256;
            int mi = e >> 5, ki = e & 31;
            float v = x[(size_t)(m0 + mi) * D_ + k0 + ki];
            Ast[mi * 33 + ki] = v * sSc[mi] + sSh[mi];
        }
        #pragma unroll
        for (int i = 0; i < 4; ++i) {
            int e = tid + i * 256;
            int ki = e >> 5, ni = e & 31;
            Bst[ki * 32 + ni] = W1[(size_t)(k0 + ki) * H_ + n0 + ni];
        }
        __syncthreads();
        #pragma unroll
        for (int kk = 0; kk < 32; ++kk) {
            float b0 = Bst[kk * 32 + ng * 2];
            float b1v = Bst[kk * 32 + ng * 2 + 1];
            #pragma unroll
            for (int i = 0; i < 4; ++i) {
                float a = Ast[(mg * 4 + i) * 33 + kk];
                acc[i][0] = fmaf(a, b0, acc[i][0]);
                acc[i][1] = fmaf(a, b1v, acc[i][1]);
            }
        }
        __syncthreads();
    }
    #pragma unroll
    for (int j = 0; j < 2; ++j) {
        int n = n0 + ng * 2 + j;          // hidden index = k of big GEMMs
        float bb = b1[n];
        #pragma unroll
        for (int i = 0; i < 4; ++i) {
            int m = m0 + mg * 4 + i;
            float hv = fmaxf(acc[i][j] + bb, 0.f);
            __nv_bfloat16 hi = __float2bfloat16(hv);
            __nv_bfloat16 lo = __float2bfloat16(hv - __bfloat162float(hi));
            g_hhi[(size_t)m * H_ + n] = hi;
            g_hlo[(size_t)m * H_ + n] = lo;
        }
    }
}

// ---------------- Kernels 3 & 4: pipelined bf16 HMMA GEMM (R12 architecture) -----------
// 256 threads (8 warps: 2m x 4n), block tile M=128 x N=64, KC=32, 16 chunks.
// MODE 0 (v GEMM): SINGLE bf16 MMA (Ah·Bh). Error budget: the gather averages 32
//   independent v rows (÷√32) and slm is ×0.1 vs y -> output contribution ~6e-5.
//   Stage = Ah(10,240) + Bh(4,608) = 14,848 B; 2 stages; 3 CTAs/SM.
// MODE 1 (y GEMM): 3-MMA hi/lo split (exact path to 2^-17 per product).
//   Stage = Ah + Al + Bh + Bl = 29,696 B; 2 stages; 2 CTAs/SM.
// W path register-resident; 1 syncthreads per chunk (proven R12 scheme).
#define KC_    32
#define NCH    (H_ / KC_)          // 16
#define AROWB  80
#define BROWB  144

template<int MODE>
__global__ __launch_bounds__(256, (MODE == 0) ? 3 : 2)
void mma_gemm_kernel(const float* __restrict__ W,
                     const float* __restrict__ bias,
                     const float* __restrict__ slw,
                     const int*   __restrict__ slidx,
                     float* __restrict__ out,
                     int Nfull)
{
    constexpr uint32_t OFF_AL = 10240;                           // mode1 only
    constexpr uint32_t OFF_BH = (MODE == 0) ? 10240u : 20480u;
    constexpr uint32_t OFF_BL = 25088;                           // mode1 only
    constexpr uint32_t STG    = (MODE == 0) ? 14848u : 29696u;

    extern __shared__ __align__(16) unsigned char dynsmem[];
    __shared__ int   sIdx[8][32];
    __shared__ float sWt[8][32];

    const int tid = threadIdx.x;
    const int wid = tid >> 5;
    const int lid = tid & 31;
    const int wm = wid >> 2;            // 0..1  -> m offset wm*64
    const int wn = wid & 3;             // 0..3  -> n offset wn*16
    const int n0 = blockIdx.x * 64;

    const uint32_t sb = (uint32_t)__cvta_generic_to_shared(dynsmem);

    // this thread's W granules: e0 = tid, e1 = tid + 256; k = e>>4, n4 = (e&15)*4
    const int k_a = tid >> 4,          n4_a = (tid & 15) * 4;
    const int k_b = (tid + 256) >> 4;
    const bool okN = (MODE == 0) || (n0 + n4_a < Nfull);   // Nfull%4==0 -> all-or-nothing

    float4 wra, wrb;                    // W prefetch registers (chunk c+1)

    auto ldg_w = [&](int c) {
        const float* Wc = W + (size_t)(c * KC_) * Nfull + n0 + n4_a;
        wra = okN ? *(const float4*)(Wc + (size_t)k_a * Nfull) : make_float4(0.f,0.f,0.f,0.f);
        wrb = okN ? *(const float4*)(Wc + (size_t)k_b * Nfull) : make_float4(0.f,0.f,0.f,0.f);
    };
    auto sts_b = [&](int buf) {
        const uint32_t base = sb + buf * STG;
        #pragma unroll
        for (int t = 0; t < 2; ++t) {
            float4 wv = t ? wrb : wra;
            int k = t ? k_b : k_a;
            __nv_bfloat162 h01 = __floats2bfloat162_rn(wv.x, wv.y);
            __nv_bfloat162 h23 = __floats2bfloat162_rn(wv.z, wv.w);
            uint32_t d = k * BROWB + n4_a * 2;
            sts64(base + OFF_BH + d, *reinterpret_cast<uint32_t*>(&h01),
                                     *reinterpret_cast<uint32_t*>(&h23));
            if (MODE == 1) {
                float2 fh01 = __bfloat1622float2(h01);
                float2 fh23 = __bfloat1622float2(h23);
                __nv_bfloat162 l01 = __floats2bfloat162_rn(wv.x - fh01.x, wv.y - fh01.y);
                __nv_bfloat162 l23 = __floats2bfloat162_rn(wv.z - fh23.x, wv.w - fh23.y);
                sts64(base + OFF_BL + d, *reinterpret_cast<uint32_t*>(&l01),
                                         *reinterpret_cast<uint32_t*>(&l23));
            }
        }
    };
    auto issue_a = [&](int c, int buf) {
        const uint32_t base = sb + buf * STG;
        const int k0b = c * KC_ * 2;
        #pragma unroll
        for (int t = 0; t < 2; ++t) {
            int e = tid + t * 256;               // 0..511
            int m = e >> 2, g = e & 3;
            uint32_t d = m * AROWB + g * 16;
            cpa16(base + d, (const char*)g_hhi + (size_t)m * (H_ * 2) + k0b + g * 16);
            if (MODE == 1)
                cpa16(base + OFF_AL + d,
                      (const char*)g_hlo + (size_t)m * (H_ * 2) + k0b + g * 16);
        }
        cpa_commit();
    };

    float acc[4][2][4];
    #pragma unroll
    for (int t = 0; t < 4; ++t)
        #pragma unroll
        for (int u = 0; u < 2; ++u)
            #pragma unroll
            for (int q = 0; q < 4; ++q) acc[t][u][q] = 0.f;

    // ---- prologue ----
    ldg_w(0);
    sts_b(0);                 // B(0)
    issue_a(0, 0);
    ldg_w(1);
    cpa_wait0();              // A(0) resident (own granules)
    __syncthreads();          // A(0), B(0) visible to all
    issue_a(1, 1);

    for (int c = 0; c < NCH; ++c) {
        const int buf = c & 1;
        const uint32_t base = sb + buf * STG;

        if (c + 1 < NCH) sts_b((c + 1) & 1);     // publish B(c+1) (own regs)

        // ---- MMA(c) ----
        #pragma unroll
        for (int ks = 0; ks < 2; ++ks) {
            uint32_t baddr = base + OFF_BH
                + (uint32_t)((ks * 16 + (lid & 7) + ((lid >> 3) & 1) * 8) * BROWB
                             + (wn * 16 + (lid >> 4) * 8) * 2);
            uint32_t bh[4], bl[4];
            ldsm_x4_t(bh, baddr);
            if (MODE == 1) ldsm_x4_t(bl, baddr + (OFF_BL - OFF_BH));
            #pragma unroll
            for (int t = 0; t < 4; ++t) {
                uint32_t aaddr = base
                    + (uint32_t)((wm * 64 + t * 16 + (lid & 15)) * AROWB
                                 + (ks * 16 + (lid >> 4) * 8) * 2);
                uint32_t ah[4];
                ldsm_x4(ah, aaddr);
                if (MODE == 1) {
                    uint32_t al[4];
                    ldsm_x4(al, aaddr + OFF_AL);
                    // interleaved: same-acc chains at distance 2
                    mma16816(acc[t][0], ah, bh[0], bh[1]);
                    mma16816(acc[t][1], ah, bh[2], bh[3]);
                    mma16816(acc[t][0], ah, bl[0], bl[1]);
                    mma16816(acc[t][1], ah, bl[2], bl[3]);
                    mma16816(acc[t][0], al, bh[0], bh[1]);
                    mma16816(acc[t][1], al, bh[2], bh[3]);
                } else {
                    mma16816(acc[t][0], ah, bh[0], bh[1]);
                    mma16816(acc[t][1], ah, bh[2], bh[3]);
                }
            }
        }

        if (c + 2 < NCH) ldg_w(c + 2);           // W prefetch for chunk c+2
        if (c + 1 < NCH) cpa_wait0();            // A(c+1) resident
        __syncthreads();                         // rotate buffers
        if (c + 2 < NCH) issue_a(c + 2, buf);    // A(c) readers done
    }

    // ---------------- epilogues (reuse dynsmem) ----------------
    if (MODE == 0) {
        float* Ct = (float*)dynsmem;               // [64 n][132 m] = 33,792 B
        #pragma unroll
        for (int t = 0; t < 4; ++t)
            #pragma unroll
            for (int u = 0; u < 2; ++u) {
                int row = wm * 64 + t * 16 + (lid >> 2);
                int col = wn * 16 + u * 8 + (lid & 3) * 2;
                Ct[(col    ) * 132 + row    ] = acc[t][u][0];
                Ct[(col + 1) * 132 + row    ] = acc[t][u][1];
                Ct[(col    ) * 132 + row + 8] = acc[t][u][2];
                Ct[(col + 1) * 132 + row + 8] = acc[t][u][3];
            }
        __syncthreads();
        #pragma unroll
        for (int it = 0; it < 8; ++it) {
            int e = tid + it * 256;                // 64 n x 32 m-quads
            int nl = e >> 5, mu = (e & 31) * 4;
            float bs = bias[n0 + nl];
            float4 v = *(const float4*)&Ct[nl * 132 + mu];
            __nv_bfloat162 p0 = __floats2bfloat162_rn(v.x + bs, v.y + bs);
            __nv_bfloat162 p1 = __floats2bfloat162_rn(v.z + bs, v.w + bs);
            uint2 pk;
            pk.x = *reinterpret_cast<uint32_t*>(&p0);
            pk.y = *reinterpret_cast<uint32_t*>(&p1);
            *(uint2*)(g_vt16 + (size_t)(n0 + nl) * M_ + mu) = pk;
        }
    } else {
        float* Cs = (float*)dynsmem;               // [128 m][65 n]
        #pragma unroll
        for (int t = 0; t < 4; ++t)
            #pragma unroll
            for (int u = 0; u < 2; ++u) {
                int row = wm * 64 + t * 16 + (lid >> 2);
                int col = wn * 16 + u * 8 + (lid & 3) * 2;
                Cs[(row    ) * 65 + col    ] = acc[t][u][0];
                Cs[(row    ) * 65 + col + 1] = acc[t][u][1];
                Cs[(row + 8) * 65 + col    ] = acc[t][u][2];
                Cs[(row + 8) * 65 + col + 1] = acc[t][u][3];
            }
        __syncthreads();

        // coalesced sparse gather-add (512B/warp g_vt16 reads)
        #pragma unroll 1
        for (int si = 0; si < 8; ++si) {
            int nl = wid * 8 + si;
            int s = n0 + nl;
            if (s < Nfull) {                       // warp-uniform
                sIdx[wid][lid] = slidx[(size_t)s * K_ + lid];
                sWt[wid][lid]  = slw  [(size_t)s * K_ + lid] * SLM_SCALE;
                __syncwarp();
                float ax = 0.f, ay = 0.f, az = 0.f, aw = 0.f;
                #pragma unroll
                for (int k = 0; k < K_; ++k) {
                    int   ix = sIdx[wid][k];
                    float wk = sWt[wid][k];
                    uint2 pk = *(const uint2*)(g_vt16 + (size_t)ix * M_ + lid * 4);
                    __nv_bfloat162 q0 = *reinterpret_cast<__nv_bfloat162*>(&pk.x);
                    __nv_bfloat162 q1 = *reinterpret_cast<__nv_bfloat162*>(&pk.y);
                    float2 f0 = __bfloat1622float2(q0);
                    float2 f1 = __bfloat1622float2(q1);
                    ax = fmaf(wk, f0.x, ax);
                    ay = fmaf(wk, f0.y, ay);
                    az = fmaf(wk, f1.x, az);
                    aw = fmaf(wk, f1.y, aw);
                }
                int mB = lid * 4;
                Cs[(mB + 0) * 65 + nl] += ax;
                Cs[(mB + 1) * 65 + nl] += ay;
                Cs[(mB + 2) * 65 + nl] += az;
                Cs[(mB + 3) * 65 + nl] += aw;
                __syncwarp();
            }
        }
        __syncthreads();
        for (int e = tid; e < 128 * 64; e += 256) {
            int m = e >> 6, nl = e & 63;
            int n = n0 + nl;
            if (n < Nfull)
                out[(size_t)m * Nfull + n] = Cs[m * 65 + nl] + bias[n];
        }
    }
}

// ---------------- launch ----------------
extern "C" void kernel_launch(void* const* d_in, const int* in_sizes, int n_in,
                              void* d_out, int out_size)
{
    const float* x     = (const float*)d_in[0];   // cached_embeddings [2,64,1024]
    const float* gamma = (const float*)d_in[1];   // bn_gamma [64]
    const float* beta  = (const float*)d_in[2];   // bn_beta  [64]
    const float* W1    = (const float*)d_in[3];   // [1024,512]
    const float* b1    = (const float*)d_in[4];   // [512]
    const float* W2    = (const float*)d_in[5];   // [512,50000]
    const float* b2    = (const float*)d_in[6];   // [50000]
    const float* Wslm  = (const float*)d_in[7];   // [512,40000]
    const float* bslm  = (const float*)d_in[8];   // [40000]
    const float* slw   = (const float*)d_in[9];   // [50000,32]
    const int*   slidx = (const int*)d_in[10];    // [50000,32]
    float* out = (float*)d_out;

    const int DYN0 = 64 * 132 * 4;                // 33,792 B (epilogue > 2*14,848 ring)
    const int DYN1 = 2 * 29696;                   // 59,392 B
    cudaFuncSetAttribute(mma_gemm_kernel<0>, cudaFuncAttributeMaxDynamicSharedMemorySize, DYN0);
    cudaFuncSetAttribute(mma_gemm_kernel<1>, cudaFuncAttributeMaxDynamicSharedMemorySize, DYN1);

    bn_stats_kernel<<<L_, 256>>>(x, gamma, beta);
    h_gemm_kernel<<<dim3(2, 16), 256>>>(x, W1, b1);
    mma_gemm_kernel<0><<<V_ / 64, 256, DYN0>>>(Wslm, bslm, nullptr, nullptr, nullptr, V_);
    mma_gemm_kernel<1><<<(S_ + 63) / 64, 256, DYN1>>>(W2, b2, slw, slidx, out, S_);
}